// round 5
// baseline (speedup 1.0000x reference)
#include <cuda_runtime.h>
#include <cuda_bf16.h>

// MLLoss: per-sample hinge loss over [B,16] f32 distances -> scalar mean.
// Labels int32. HBM-bound: 288 MB read.
//
// R5: coalesced loads (R4) + SHUFFLE-FREE chunk decomposition:
//   total = sum over (row,chunk) of (dl<=1)*s_chunk  +  sum over rows of rowterm
// Each lane owns a quarter-row; only the chunk-0 lane adds the row term
// (d0,d1,h0,h1 are in its own float4). Labels via quad-broadcast gather.
// Single kernel, last-block finalization.

#define THREADS 256
#define BLOCKS  2048

__device__ float        g_partial;   // zero at load; reset by last block each call
__device__ unsigned int g_count;

__global__ __launch_bounds__(THREADS)
void mlloss_kernel(const float4* __restrict__ dist4,  // [B,16] as B*4 float4
                   const int* __restrict__ doctor,    // [B] int32 {0,1,2}
                   const int* __restrict__ real_l,    // [B] int32 {0,1}
                   float* __restrict__ out,
                   int B, float inv_B)
{
    const int lane    = threadIdx.x & 31;
    const bool is_c0  = (lane & 3) == 0;   // this lane holds cols 0..3 of its row
    const int row_off = lane >> 2;          // 0..7 within each 8-row group

    const int warp_id   = (blockIdx.x * blockDim.x + threadIdx.x) >> 5;
    const int num_warps = (gridDim.x * blockDim.x) >> 5;
    const int nchunks   = B >> 5;            // 32 rows per warp-iteration

    float acc = 0.0f;

    for (int it = warp_id; it < nchunks; it += num_warps) {
        const int row_base = it << 5;
        const size_t f4    = (size_t)row_base << 2;   // 128 float4 = 2KB contiguous

        // front-batched loads: 4x coalesced LDG.128 + 8x broadcast label LDG
        float4 v[4];
        #pragma unroll
        for (int u = 0; u < 4; u++)
            v[u] = dist4[f4 + u * 32 + lane];

        int dl[4], rl[4];
        #pragma unroll
        for (int u = 0; u < 4; u++) {
            const int r = row_base + u * 8 + row_off;  // this lane's row for step u
            dl[u] = doctor[r];
            rl[u] = real_l[r];
        }

        #pragma unroll
        for (int u = 0; u < 4; u++) {
            const float4 x = v[u];
            const float h0 = fmaxf(1.0f - x.x, 0.0f);
            const float h1 = fmaxf(1.0f - x.y, 0.0f);
            const float h2 = fmaxf(1.0f - x.z, 0.0f);
            const float h3 = fmaxf(1.0f - x.w, 0.0f);
            const float s  = (h0 + h1) + (h2 + h3);

            // hinge-sum part: every chunk of rows with dl in {0,1}
            float contrib = (dl[u] <= 1) ? s : 0.0f;

            // row term: only the lane holding columns 0..3
            if (is_c0) {
                contrib += (dl[u] == 0) ? (x.x - h0)
                         : (dl[u] == 1) ? (x.y - h1)
                                        : ((rl[u] == 0) ? h1 : h0);
            }
            acc += contrib;
        }
    }

    // tail rows (B % 32) — scalar, block 0 only
    const int tail_start = nchunks << 5;
    if (blockIdx.x == 0) {
        for (int row = tail_start + threadIdx.x; row < B; row += blockDim.x) {
            const size_t base = (size_t)row * 4;
            const float4 a = dist4[base + 0], b = dist4[base + 1];
            const float4 c = dist4[base + 2], d = dist4[base + 3];
            const float h0 = fmaxf(1.0f - a.x, 0.0f);
            const float h1 = fmaxf(1.0f - a.y, 0.0f);
            float hs = h0 + h1
                     + fmaxf(1.0f - a.z, 0.0f) + fmaxf(1.0f - a.w, 0.0f)
                     + fmaxf(1.0f - b.x, 0.0f) + fmaxf(1.0f - b.y, 0.0f)
                     + fmaxf(1.0f - b.z, 0.0f) + fmaxf(1.0f - b.w, 0.0f)
                     + fmaxf(1.0f - c.x, 0.0f) + fmaxf(1.0f - c.y, 0.0f)
                     + fmaxf(1.0f - c.z, 0.0f) + fmaxf(1.0f - c.w, 0.0f)
                     + fmaxf(1.0f - d.x, 0.0f) + fmaxf(1.0f - d.y, 0.0f)
                     + fmaxf(1.0f - d.z, 0.0f) + fmaxf(1.0f - d.w, 0.0f);
            const int dlv = doctor[row], rlv = real_l[row];
            acc += (dlv == 0) ? (a.x + hs - h0)
                 : (dlv == 1) ? (a.y + hs - h1)
                              : ((rlv == 0) ? h1 : h0);
        }
    }

    // warp reduce
    #pragma unroll
    for (int off = 16; off > 0; off >>= 1)
        acc += __shfl_xor_sync(0xFFFFFFFFu, acc, off);

    __shared__ float warp_sums[THREADS / 32];
    const int wid = threadIdx.x >> 5;
    if (lane == 0) warp_sums[wid] = acc;
    __syncthreads();

    if (wid == 0) {
        float vsum = (lane < THREADS / 32) ? warp_sums[lane] : 0.0f;
        #pragma unroll
        for (int off = 16; off > 0; off >>= 1)
            vsum += __shfl_xor_sync(0xFFFFFFFFu, vsum, off);

        if (lane == 0) {
            atomicAdd(&g_partial, vsum);
            __threadfence();
            const unsigned int ticket = atomicAdd(&g_count, 1u);
            if (ticket == gridDim.x - 1) {
                const float total = atomicAdd(&g_partial, 0.0f); // fenced read
                out[0] = total * inv_B;
                g_partial = 0.0f;
                g_count   = 0u;
                __threadfence();
            }
        }
    }
}

extern "C" void kernel_launch(void* const* d_in, const int* in_sizes, int n_in,
                              void* d_out, int out_size)
{
    const float4* dist4  = (const float4*)d_in[0];
    const int*    doctor = (const int*)d_in[1];
    const int*    real_l = (const int*)d_in[2];
    float*        out    = (float*)d_out;

    const int B = in_sizes[1];
    const float inv_B = 1.0f / (float)B;

    mlloss_kernel<<<BLOCKS, THREADS>>>(dist4, doctor, real_l, out, B, inv_B);
}

// round 6
// speedup vs baseline: 1.2121x; 1.2121x over previous
#include <cuda_runtime.h>
#include <cuda_bf16.h>

// MLLoss: per-sample hinge loss over [B,16] f32 distances -> scalar mean.
// Labels int32. HBM-bound: 288 MB read.
//
// R6 = R2 (best known: 49.2us kernel, DRAM 78.5%) + three targeted fixes:
//  - single-wave grid: 1216 blocks (8/SM x 152 SMs), grid-stride loop
//    (kills the 1.7-wave partial-wave sag of the 2048-block launch)
//  - in-kernel last-block finalization (drops the zero_out launch, ~2.4us)
//  - __ldcs streaming loads (read-once data, evict-first)

#define THREADS 256
#define BLOCKS  1216   // 8 blocks/SM x 152 SMs = one full wave

__device__ float        g_partial;   // zero at load; reset by last block each call
__device__ unsigned int g_count;

__global__ __launch_bounds__(THREADS, 8)
void mlloss_kernel(const float4* __restrict__ dist4,  // [B,16] as B*4 float4
                   const int* __restrict__ doctor,    // [B] int32 {0,1,2}
                   const int* __restrict__ real_l,    // [B] int32 {0,1}
                   float* __restrict__ out,
                   int B, float inv_B)
{
    const int tid    = blockIdx.x * blockDim.x + threadIdx.x;
    const int stride = gridDim.x * blockDim.x;

    float acc = 0.0f;

    for (int row = tid; row < B; row += stride) {
        const size_t base = (size_t)row * 4;
        const float4 a = __ldcs(&dist4[base + 0]);
        const float4 b = __ldcs(&dist4[base + 1]);
        const float4 c = __ldcs(&dist4[base + 2]);
        const float4 d = __ldcs(&dist4[base + 3]);
        const int   dl = __ldcs(&doctor[row]);
        const int   rl = __ldcs(&real_l[row]);

        const float h0 = fmaxf(1.0f - a.x, 0.0f);
        const float h1 = fmaxf(1.0f - a.y, 0.0f);
        float hs = h0 + h1
                 + fmaxf(1.0f - a.z, 0.0f) + fmaxf(1.0f - a.w, 0.0f)
                 + fmaxf(1.0f - b.x, 0.0f) + fmaxf(1.0f - b.y, 0.0f)
                 + fmaxf(1.0f - b.z, 0.0f) + fmaxf(1.0f - b.w, 0.0f)
                 + fmaxf(1.0f - c.x, 0.0f) + fmaxf(1.0f - c.y, 0.0f)
                 + fmaxf(1.0f - c.z, 0.0f) + fmaxf(1.0f - c.w, 0.0f)
                 + fmaxf(1.0f - d.x, 0.0f) + fmaxf(1.0f - d.y, 0.0f)
                 + fmaxf(1.0f - d.z, 0.0f) + fmaxf(1.0f - d.w, 0.0f);

        const float loss = (dl == 0) ? (a.x + hs - h0)
                         : (dl == 1) ? (a.y + hs - h1)
                                     : ((rl == 0) ? h1 : h0);
        acc += loss;
    }

    // warp reduce
    #pragma unroll
    for (int off = 16; off > 0; off >>= 1)
        acc += __shfl_xor_sync(0xFFFFFFFFu, acc, off);

    __shared__ float warp_sums[THREADS / 32];
    const int lane = threadIdx.x & 31;
    const int wid  = threadIdx.x >> 5;
    if (lane == 0) warp_sums[wid] = acc;
    __syncthreads();

    if (wid == 0) {
        float v = (lane < THREADS / 32) ? warp_sums[lane] : 0.0f;
        #pragma unroll
        for (int off = 16; off > 0; off >>= 1)
            v += __shfl_xor_sync(0xFFFFFFFFu, v, off);

        if (lane == 0) {
            atomicAdd(&g_partial, v);
            __threadfence();
            const unsigned int ticket = atomicAdd(&g_count, 1u);
            if (ticket == gridDim.x - 1) {
                const float total = atomicAdd(&g_partial, 0.0f); // fenced read
                out[0] = total * inv_B;
                g_partial = 0.0f;
                g_count   = 0u;
                __threadfence();
            }
        }
    }
}

extern "C" void kernel_launch(void* const* d_in, const int* in_sizes, int n_in,
                              void* d_out, int out_size)
{
    const float4* dist4  = (const float4*)d_in[0];
    const int*    doctor = (const int*)d_in[1];
    const int*    real_l = (const int*)d_in[2];
    float*        out    = (float*)d_out;

    const int B = in_sizes[1];
    const float inv_B = 1.0f / (float)B;

    mlloss_kernel<<<BLOCKS, THREADS>>>(dist4, doctor, real_l, out, B, inv_B);
}